// round 1
// baseline (speedup 1.0000x reference)
#include <cuda_runtime.h>
#include <math.h>
#include <stdint.h>

// ---------------------------------------------------------------------------
// SOMFNN: two layers of (ALMMo codebook lamb) + sigmoid(Linear)
// Key algebraic facts (derived from the reference scan):
//   * stau == base/2, a per-layer scalar (SENc - cn2 == 0 invariantly)
//   * prototypes are input samples; all distances come from Gram = X X^T
//   * a sample whose min distance to ALL predecessors exceeds the density
//     threshold is a new rule independent of scan history (subset monotone)
// ---------------------------------------------------------------------------

#define MAXN 2048
#define MAXD 2048

__device__ float g_G[(size_t)MAXN * MAXN];     // Gram matrix scratch (16 MB)
__device__ float g_H[(size_t)MAXN * MAXD];     // hidden activations (16 MB)
__device__ float g_SEN[MAXN];
__device__ float g_colsum[MAXD];
__device__ float g_base[2];                    // [0]=base, [1]=stau
__device__ float g_mind[MAXN];                 // min_{j<i} D[i,j]
__device__ int   g_rules[MAXN];
__device__ int   g_protos[MAXN];
__device__ int   g_count[1];

// ---------------- block reductions ----------------
__device__ __forceinline__ float blockReduceSum(float v) {
    __shared__ float sh[32];
    int lane = threadIdx.x & 31;
    int wid  = threadIdx.x >> 5;
#pragma unroll
    for (int o = 16; o; o >>= 1) v += __shfl_down_sync(0xffffffffu, v, o);
    __syncthreads();
    if (lane == 0) sh[wid] = v;
    __syncthreads();
    if (wid == 0) {
        int nw = (blockDim.x + 31) >> 5;
        v = (lane < nw) ? sh[lane] : 0.0f;
#pragma unroll
        for (int o = 16; o; o >>= 1) v += __shfl_down_sync(0xffffffffu, v, o);
    }
    return v;  // valid at thread 0
}

__device__ __forceinline__ float blockReduceMin(float v) {
    __shared__ float sh[32];
    int lane = threadIdx.x & 31;
    int wid  = threadIdx.x >> 5;
#pragma unroll
    for (int o = 16; o; o >>= 1) v = fminf(v, __shfl_down_sync(0xffffffffu, v, o));
    __syncthreads();
    if (lane == 0) sh[wid] = v;
    __syncthreads();
    if (wid == 0) {
        int nw = (blockDim.x + 31) >> 5;
        v = (lane < nw) ? sh[lane] : INFINITY;
#pragma unroll
        for (int o = 16; o; o >>= 1) v = fminf(v, __shfl_down_sync(0xffffffffu, v, o));
    }
    return v;  // valid at thread 0
}

// ---------------- row squared norms ----------------
__global__ void rowsumsq_kernel(const float* __restrict__ X, int K) {
    int i = blockIdx.x;
    const float4* row = (const float4*)(X + (size_t)i * K);
    float s = 0.0f;
    for (int k = threadIdx.x; k < (K >> 2); k += blockDim.x) {
        float4 v = row[k];
        s += v.x * v.x + v.y * v.y + v.z * v.z + v.w * v.w;
    }
    s = blockReduceSum(s);
    if (threadIdx.x == 0) g_SEN[i] = s;
}

// ---------------- column sums (for gmean) ----------------
__global__ void colsum_kernel(const float* __restrict__ X, int N, int K) {
    int c = blockIdx.x * blockDim.x + threadIdx.x;
    if (c >= K) return;
    float s = 0.0f;
    for (int i = 0; i < N; i++) s += X[(size_t)i * K + c];
    g_colsum[c] = s;
}

// ---------------- base = mean(SEN) - ||gmean||^2 ----------------
__global__ void base_kernel(int N, int K) {
    float invN = 1.0f / (float)N;
    float s1 = 0.0f, s2 = 0.0f;
    for (int i = threadIdx.x; i < N; i += blockDim.x) s1 += g_SEN[i];
    for (int c = threadIdx.x; c < K; c += blockDim.x) {
        float m = g_colsum[c] * invN;
        s2 += m * m;
    }
    s1 = blockReduceSum(s1);
    __syncthreads();
    s2 = blockReduceSum(s2);
    if (threadIdx.x == 0) {
        float base = s1 * invN - s2;
        g_base[0] = base;
        g_base[1] = 0.5f * base;
    }
}

// ---------------- tiled fp32 GEMM (NT): C[i,j] = sum_k A[i,k]*B[j,k] -------
// M,N multiples of 128; K multiple of 8. Optional fused bias + sigmoid.
__global__ void __launch_bounds__(256)
gemm_nt_kernel(const float* __restrict__ A, const float* __restrict__ B,
               float* __restrict__ C, int M, int N, int K,
               const float* __restrict__ bias, int act) {
    __shared__ float As[8][128];
    __shared__ float Bs[8][128];
    const int tid = threadIdx.x;
    const int tx = tid & 15;        // 0..15 (column group)
    const int ty = tid >> 4;        // 0..15 (row group)
    const int lr = tid >> 1;        // 0..127 load row
    const int lc = (tid & 1) << 2;  // 0 or 4 load k offset
    const int rowBase = blockIdx.y << 7;
    const int colBase = blockIdx.x << 7;

    const float* Ap = A + (size_t)(rowBase + lr) * K + lc;
    const float* Bp = B + (size_t)(colBase + lr) * K + lc;

    float acc[8][8];
#pragma unroll
    for (int m = 0; m < 8; m++)
#pragma unroll
        for (int n = 0; n < 8; n++) acc[m][n] = 0.0f;

    for (int k0 = 0; k0 < K; k0 += 8) {
        float4 av = *(const float4*)Ap; Ap += 8;
        float4 bv = *(const float4*)Bp; Bp += 8;
        __syncthreads();
        As[lc + 0][lr] = av.x; As[lc + 1][lr] = av.y;
        As[lc + 2][lr] = av.z; As[lc + 3][lr] = av.w;
        Bs[lc + 0][lr] = bv.x; Bs[lc + 1][lr] = bv.y;
        Bs[lc + 2][lr] = bv.z; Bs[lc + 3][lr] = bv.w;
        __syncthreads();
#pragma unroll
        for (int kk = 0; kk < 8; kk++) {
            float a[8], b[8];
            *(float4*)(a)     = *(const float4*)&As[kk][ty * 8];
            *(float4*)(a + 4) = *(const float4*)&As[kk][ty * 8 + 4];
            *(float4*)(b)     = *(const float4*)&Bs[kk][tx * 8];
            *(float4*)(b + 4) = *(const float4*)&Bs[kk][tx * 8 + 4];
#pragma unroll
            for (int m = 0; m < 8; m++)
#pragma unroll
                for (int n = 0; n < 8; n++) acc[m][n] += a[m] * b[n];
        }
    }

    float bb[8];
    if (act) {
#pragma unroll
        for (int n = 0; n < 8; n++) bb[n] = bias[colBase + tx * 8 + n];
    }
#pragma unroll
    for (int m = 0; m < 8; m++) {
        int r = rowBase + ty * 8 + m;
        float* Crow = C + (size_t)r * N + colBase + tx * 8;
        float v[8];
#pragma unroll
        for (int n = 0; n < 8; n++) {
            float s = acc[m][n];
            if (act) {
                s += bb[n];
                s = 1.0f / (1.0f + expf(-s));
            }
            v[n] = s;
        }
        *(float4*)(Crow)     = *(float4*)(v);
        *(float4*)(Crow + 4) = *(float4*)(v + 4);
    }
}

// ---------------- prefix row-min: min_{j<i} D[i,j] ----------------
__global__ void prefixmin_kernel(int N) {
    int i = blockIdx.x;
    float si = g_SEN[i];
    const float* Gi = g_G + (size_t)i * N;
    float m = INFINITY;
    for (int j = threadIdx.x; j < i; j += blockDim.x) {
        float d = si + g_SEN[j] - 2.0f * Gi[j];
        m = fminf(m, d);
    }
    m = blockReduceMin(m);
    if (threadIdx.x == 0) g_mind[i] = m;
}

// ---------------- sequential rule-creation scan (1 warp) ----------------
__global__ void scan_kernel(int N) {
    const int lane = threadIdx.x;
    const float DELTA = 0.13533528323661270f;  // exp(-2)
    float stau = g_base[1];
    bool st_ok = (stau > 0.0f) && (stau < 3.0e38f);
    int count = 0;

    for (int i0 = 0; i0 < N; i0 += 32) {
        int myi = i0 + lane;
        float myd = (myi < N) ? g_mind[myi] : 0.0f;  // prefetch a batch of 32
        int lim = (N - i0 < 32) ? (N - i0) : 32;
        for (int t = 0; t < lim; t++) {
            int i = i0 + t;
            float mind_all = __shfl_sync(0xffffffffu, myd, t);
            bool newr;
            int slot = 0;
            if (count == 0) {
                newr = true;
            } else if (st_ok && (expf(-mind_all / stau) < DELTA)) {
                // min over ALL predecessors already below threshold =>
                // min over the prototype subset is too => new rule, certain.
                newr = true;
            } else {
                // faithful evaluation over current prototype set
                float si = g_SEN[i];
                const float* Gi = g_G + (size_t)i * N;
                float best = -INFINITY;
                int bestr = 0x7fffffff;
                for (int r = lane; r < count; r += 32) {
                    int p = g_protos[r];
                    float d = si + g_SEN[p] - 2.0f * Gi[p];
                    float dens = expf(-d / stau);
                    if (dens > best) { best = dens; bestr = r; }  // keep first max
                }
#pragma unroll
                for (int off = 16; off; off >>= 1) {
                    float ob = __shfl_down_sync(0xffffffffu, best, off);
                    int obr = __shfl_down_sync(0xffffffffu, bestr, off);
                    if (ob > best || (ob == best && obr < bestr)) { best = ob; bestr = obr; }
                }
                best  = __shfl_sync(0xffffffffu, best, 0);
                bestr = __shfl_sync(0xffffffffu, bestr, 0);
                newr = (best < DELTA);
                slot = bestr;
            }
            if (newr) slot = count;
            if (lane == 0) g_rules[i] = slot;
            if (newr) {
                if (lane == 0) g_protos[count] = i;
                count++;
            }
        }
    }
    if (lane == 0) g_count[0] = count;
}

// ---------------- final normalized densities ----------------
__global__ void lamb_kernel(int N, float* __restrict__ out) {
    int n = blockIdx.x;
    int count = g_count[0];
    float stau = g_base[1];
    float sn = g_SEN[n];
    const float* Gn = g_G + (size_t)n * N;  // Gram is symmetric (bitwise: same k-order)
    float s = 0.0f;
    for (int r = threadIdx.x; r < count; r += blockDim.x) {
        int p = g_protos[r];
        float d = sn + g_SEN[p] - 2.0f * Gn[p];
        s += expf(-d / stau);
    }
    s = blockReduceSum(s);
    if (threadIdx.x == 0) {
        int p = g_protos[g_rules[n]];
        float d = sn + g_SEN[p] - 2.0f * Gn[p];
        out[n] = expf(-d / stau) / s;
    }
}

// ---------------- host-side orchestration ----------------
static void run_codebook(const float* X, int N, int K, float* lamb_out, float* Gptr) {
    rowsumsq_kernel<<<N, 256>>>(X, K);
    colsum_kernel<<<(K + 255) / 256, 256>>>(X, N, K);
    base_kernel<<<1, 256>>>(N, K);
    dim3 gg(N / 128, N / 128);
    gemm_nt_kernel<<<gg, 256>>>(X, X, Gptr, N, N, K, nullptr, 0);
    prefixmin_kernel<<<N, 256>>>(N);
    scan_kernel<<<1, 32>>>(N);
    lamb_kernel<<<N, 256>>>(N, lamb_out);
}

extern "C" void kernel_launch(void* const* d_in, const int* in_sizes, int n_in,
                              void* d_out, int out_size) {
    const float* x  = (const float*)d_in[0];
    const float* W0 = (const float*)d_in[1];
    const float* b0 = (const float*)d_in[2];
    const float* W1 = (const float*)d_in[3];
    const float* b1 = (const float*)d_in[4];

    int DH   = in_sizes[2];            // 2048
    int DOUT = in_sizes[4];            // 1024
    int DIN  = in_sizes[1] / DH;       // 2048
    int N    = in_sizes[0] / DIN;      // 2048

    float* out   = (float*)d_out;
    float* outH  = out;                          // h: [N, DOUT]
    float* lamb0 = out + (size_t)N * DOUT;       // lambs[0]: [N]
    float* lamb1 = lamb0 + N;                    // lambs[1]: [N]

    float* Gptr = nullptr;
    float* Hptr = nullptr;
    cudaGetSymbolAddress((void**)&Gptr, g_G);
    cudaGetSymbolAddress((void**)&Hptr, g_H);

    // ---- layer 0: codebook on x, then H = sigmoid(x W0^T + b0) ----
    run_codebook(x, N, DIN, lamb0, Gptr);
    {
        dim3 g0(DH / 128, N / 128);
        gemm_nt_kernel<<<g0, 256>>>(x, W0, Hptr, N, DH, DIN, b0, 1);
    }

    // ---- layer 1: codebook on H, then out = sigmoid(H W1^T + b1) ----
    run_codebook(Hptr, N, DH, lamb1, Gptr);
    {
        dim3 g1(DOUT / 128, N / 128);
        gemm_nt_kernel<<<g1, 256>>>(Hptr, W1, outH, N, DOUT, DH, b1, 1);
    }
}

// round 2
// speedup vs baseline: 2.0469x; 2.0469x over previous
#include <cuda_runtime.h>
#include <math.h>
#include <stdint.h>

// SOMFNN: two layers of (ALMMo codebook lamb) + sigmoid(Linear)
// Algebraic facts: stau = base/2 (scalar); prototypes are input samples so all
// distances come from Gram = X X^T; a sample whose min distance to ALL
// predecessors is beyond the density threshold is a new rule regardless of
// scan history (prototype subset monotonicity).

#define MAXN 2048
#define MAXD 2048
#define NCHUNK 16

__device__ float g_G[(size_t)MAXN * MAXN];       // Gram scratch (16 MB)
__device__ float g_H[(size_t)MAXN * MAXD];       // hidden activations
__device__ float g_SEN[MAXN];
__device__ float g_colpart[NCHUNK][MAXD];        // partial column sums
__device__ float g_base[2];                      // [0]=base, [1]=stau
__device__ float g_mind[MAXN];                   // min_{j<i} D[i,j]
__device__ int   g_rules[MAXN];
__device__ int   g_protos[MAXN];
__device__ int   g_count[1];

// ---------------- block reductions ----------------
__device__ __forceinline__ float blockReduceSum(float v) {
    __shared__ float sh[32];
    int lane = threadIdx.x & 31, wid = threadIdx.x >> 5;
#pragma unroll
    for (int o = 16; o; o >>= 1) v += __shfl_down_sync(0xffffffffu, v, o);
    __syncthreads();
    if (lane == 0) sh[wid] = v;
    __syncthreads();
    if (wid == 0) {
        int nw = (blockDim.x + 31) >> 5;
        v = (lane < nw) ? sh[lane] : 0.0f;
#pragma unroll
        for (int o = 16; o; o >>= 1) v += __shfl_down_sync(0xffffffffu, v, o);
    }
    return v;
}

__device__ __forceinline__ float blockReduceMin(float v) {
    __shared__ float sh[32];
    int lane = threadIdx.x & 31, wid = threadIdx.x >> 5;
#pragma unroll
    for (int o = 16; o; o >>= 1) v = fminf(v, __shfl_down_sync(0xffffffffu, v, o));
    __syncthreads();
    if (lane == 0) sh[wid] = v;
    __syncthreads();
    if (wid == 0) {
        int nw = (blockDim.x + 31) >> 5;
        v = (lane < nw) ? sh[lane] : INFINITY;
#pragma unroll
        for (int o = 16; o; o >>= 1) v = fminf(v, __shfl_down_sync(0xffffffffu, v, o));
    }
    return v;
}

// ---------------- row squared norms ----------------
__global__ void rowsumsq_kernel(const float* __restrict__ X, int K) {
    int i = blockIdx.x;
    const float4* row = (const float4*)(X + (size_t)i * K);
    float s = 0.0f;
    for (int k = threadIdx.x; k < (K >> 2); k += blockDim.x) {
        float4 v = row[k];
        s += v.x * v.x + v.y * v.y + v.z * v.z + v.w * v.w;
    }
    s = blockReduceSum(s);
    if (threadIdx.x == 0) g_SEN[i] = s;
}

// ---------------- chunked column sums (deterministic, parallel) ----------
__global__ void colsum_kernel(const float* __restrict__ X, int N, int K) {
    int c = blockIdx.x * blockDim.x + threadIdx.x;
    int chunk = blockIdx.y;
    if (c >= K) return;
    int r0 = chunk * (N / NCHUNK), r1 = r0 + N / NCHUNK;
    float s = 0.0f;
    for (int i = r0; i < r1; i++) s += X[(size_t)i * K + c];
    g_colpart[chunk][c] = s;
}

// ---------------- base = mean(SEN) - ||gmean||^2 ----------------
__global__ void base_kernel(int N, int K) {
    float invN = 1.0f / (float)N;
    float s1 = 0.0f, s2 = 0.0f;
    for (int i = threadIdx.x; i < N; i += blockDim.x) s1 += g_SEN[i];
    for (int c = threadIdx.x; c < K; c += blockDim.x) {
        float cs = 0.0f;
#pragma unroll
        for (int h = 0; h < NCHUNK; h++) cs += g_colpart[h][c];
        float m = cs * invN;
        s2 += m * m;
    }
    s1 = blockReduceSum(s1);
    __syncthreads();
    s2 = blockReduceSum(s2);
    if (threadIdx.x == 0) {
        float base = s1 * invN - s2;
        g_base[0] = base;
        g_base[1] = 0.5f * base;
    }
}

// ---------------- double-buffered fp32 GEMM (NT) ----------------------------
// C[i,j] = sum_k A[i,k]*B[j,k].  mode 0: plain, 1: bias+sigmoid, 2: symmetric
// Gram (A==B, triangular grid, mirrored store). M,N mult of 128, K mult of 8.
__global__ void __launch_bounds__(256, 2)
gemm_nt_kernel(const float* __restrict__ A, const float* __restrict__ B,
               float* __restrict__ C, int M, int N, int K,
               const float* __restrict__ bias, int mode) {
    __shared__ float As[2][8][128];
    __shared__ float Bs[2][8][128];
    const int tid = threadIdx.x;
    const int tx = tid & 15;
    const int ty = tid >> 4;
    const int lr = tid >> 1;
    const int lc = (tid & 1) << 2;

    int bi, bj;
    if (mode == 2) {
        int id = blockIdx.x;
        bi = (int)((sqrtf(8.0f * (float)id + 1.0f) - 1.0f) * 0.5f);
        while ((bi + 1) * (bi + 2) / 2 <= id) bi++;
        while (bi * (bi + 1) / 2 > id) bi--;
        bj = id - bi * (bi + 1) / 2;
    } else {
        bi = blockIdx.y; bj = blockIdx.x;
    }
    const int rowBase = bi << 7;
    const int colBase = bj << 7;

    const float* Ap = A + (size_t)(rowBase + lr) * K + lc;
    const float* Bp = B + (size_t)(colBase + lr) * K + lc;

    float acc[8][8];
#pragma unroll
    for (int m = 0; m < 8; m++)
#pragma unroll
        for (int n = 0; n < 8; n++) acc[m][n] = 0.0f;

    const int nt = K >> 3;
    // preload tile 0
    {
        float4 av = *(const float4*)Ap;
        float4 bv = *(const float4*)Bp;
        As[0][lc + 0][lr] = av.x; As[0][lc + 1][lr] = av.y;
        As[0][lc + 2][lr] = av.z; As[0][lc + 3][lr] = av.w;
        Bs[0][lc + 0][lr] = bv.x; Bs[0][lc + 1][lr] = bv.y;
        Bs[0][lc + 2][lr] = bv.z; Bs[0][lc + 3][lr] = bv.w;
    }
    __syncthreads();

    int p = 0;
    for (int t = 0; t < nt; t++) {
        float4 av, bv;
        if (t + 1 < nt) {
            av = *(const float4*)(Ap + (size_t)(t + 1) * 8);
            bv = *(const float4*)(Bp + (size_t)(t + 1) * 8);
        }
#pragma unroll
        for (int kk = 0; kk < 8; kk++) {
            float a[8], b[8];
            *(float4*)(a)     = *(const float4*)&As[p][kk][ty * 8];
            *(float4*)(a + 4) = *(const float4*)&As[p][kk][ty * 8 + 4];
            *(float4*)(b)     = *(const float4*)&Bs[p][kk][tx * 8];
            *(float4*)(b + 4) = *(const float4*)&Bs[p][kk][tx * 8 + 4];
#pragma unroll
            for (int m = 0; m < 8; m++)
#pragma unroll
                for (int n = 0; n < 8; n++) acc[m][n] += a[m] * b[n];
        }
        if (t + 1 < nt) {
            int q = p ^ 1;
            As[q][lc + 0][lr] = av.x; As[q][lc + 1][lr] = av.y;
            As[q][lc + 2][lr] = av.z; As[q][lc + 3][lr] = av.w;
            Bs[q][lc + 0][lr] = bv.x; Bs[q][lc + 1][lr] = bv.y;
            Bs[q][lc + 2][lr] = bv.z; Bs[q][lc + 3][lr] = bv.w;
            __syncthreads();
            p = q;
        }
    }

    if (mode == 1) {
        float bb[8];
#pragma unroll
        for (int n = 0; n < 8; n++) bb[n] = bias[colBase + tx * 8 + n];
#pragma unroll
        for (int m = 0; m < 8; m++) {
            float* Crow = C + (size_t)(rowBase + ty * 8 + m) * N + colBase + tx * 8;
            float v[8];
#pragma unroll
            for (int n = 0; n < 8; n++) {
                float s = acc[m][n] + bb[n];
                v[n] = 1.0f / (1.0f + expf(-s));
            }
            *(float4*)(Crow)     = *(float4*)(v);
            *(float4*)(Crow + 4) = *(float4*)(v + 4);
        }
    } else {
#pragma unroll
        for (int m = 0; m < 8; m++) {
            float* Crow = C + (size_t)(rowBase + ty * 8 + m) * N + colBase + tx * 8;
            *(float4*)(Crow)     = *(float4*)(&acc[m][0]);
            *(float4*)(Crow + 4) = *(float4*)(&acc[m][4]);
        }
        if (mode == 2 && bi != bj) {
            // mirror: C[col][row] = acc (identical value, deterministic)
#pragma unroll
            for (int n = 0; n < 8; n++) {
                float v[8];
#pragma unroll
                for (int m = 0; m < 8; m++) v[m] = acc[m][n];
                float* Crow = C + (size_t)(colBase + tx * 8 + n) * N + rowBase + ty * 8;
                *(float4*)(Crow)     = *(float4*)(v);
                *(float4*)(Crow + 4) = *(float4*)(v + 4);
            }
        }
    }
}

// ---------------- prefix row-min: min_{j<i} D[i,j] ----------------
__global__ void prefixmin_kernel(int N) {
    int i = blockIdx.x;
    float si = g_SEN[i];
    const float* Gi = g_G + (size_t)i * N;
    float m = INFINITY;
    for (int j = threadIdx.x; j < i; j += blockDim.x) {
        float d = si + g_SEN[j] - 2.0f * Gi[j];
        m = fminf(m, d);
    }
    m = blockReduceMin(m);
    if (threadIdx.x == 0) g_mind[i] = m;
}

// ---------------- sequential rule-creation scan (1 warp, ballot fast path) --
__global__ void scan_kernel(int N) {
    const int lane = threadIdx.x;
    const float DELTA = 0.13533528323661270f;  // exp(-2)
    float stau = g_base[1];
    bool st_ok = (stau > 0.0f) && (stau < 3.0e38f);
    int count = 0;

    for (int i0 = 0; i0 < N; i0 += 32) {
        int lim = (N - i0 < 32) ? (N - i0) : 32;
        int myi = i0 + lane;
        bool cert = false;
        if (myi < N && st_ok) cert = (expf(-g_mind[myi] / stau) < DELTA);
        unsigned mask = __ballot_sync(0xffffffffu, cert);
        unsigned need = (lim == 32) ? 0xffffffffu : ((1u << lim) - 1u);
        if ((mask & need) == need) {
            // whole word is certainly-new (subset monotonicity)
            if (lane < lim) {
                g_rules[myi]  = count + lane;
                g_protos[count + lane] = myi;
            }
            count += lim;
            continue;
        }
        for (int t = 0; t < lim; t++) {
            int i = i0 + t;
            bool newr;
            int slot = 0;
            if (count == 0 || ((mask >> t) & 1u)) {
                newr = true;
            } else {
                float si = g_SEN[i];
                const float* Gi = g_G + (size_t)i * N;
                float best = -INFINITY;
                int bestr = 0x7fffffff;
                for (int r = lane; r < count; r += 32) {
                    int pr = g_protos[r];
                    float d = si + g_SEN[pr] - 2.0f * Gi[pr];
                    float dens = expf(-d / stau);
                    if (dens > best) { best = dens; bestr = r; }
                }
#pragma unroll
                for (int off = 16; off; off >>= 1) {
                    float ob = __shfl_down_sync(0xffffffffu, best, off);
                    int obr = __shfl_down_sync(0xffffffffu, bestr, off);
                    if (ob > best || (ob == best && obr < bestr)) { best = ob; bestr = obr; }
                }
                best  = __shfl_sync(0xffffffffu, best, 0);
                bestr = __shfl_sync(0xffffffffu, bestr, 0);
                newr = (best < DELTA);
                slot = bestr;
            }
            if (newr) slot = count;
            if (lane == 0) g_rules[i] = slot;
            if (newr) {
                if (lane == 0) g_protos[count] = i;
                count++;
            }
        }
    }
    if (lane == 0) g_count[0] = count;
}

// ---------------- final normalized densities ----------------
__global__ void lamb_kernel(int N, float* __restrict__ out) {
    int n = blockIdx.x;
    int count = g_count[0];
    float stau = g_base[1];
    float sn = g_SEN[n];
    const float* Gn = g_G + (size_t)n * N;  // Gram bitwise symmetric
    float s = 0.0f;
    for (int r = threadIdx.x; r < count; r += blockDim.x) {
        int pr = g_protos[r];
        float d = sn + g_SEN[pr] - 2.0f * Gn[pr];
        s += expf(-d / stau);
    }
    s = blockReduceSum(s);
    if (threadIdx.x == 0) {
        int pr = g_protos[g_rules[n]];
        float d = sn + g_SEN[pr] - 2.0f * Gn[pr];
        out[n] = expf(-d / stau) / s;
    }
}

// ---------------- host-side orchestration ----------------
static void run_codebook(const float* X, int N, int K, float* lamb_out, float* Gptr) {
    rowsumsq_kernel<<<N, 256>>>(X, K);
    dim3 cg((K + 255) / 256, NCHUNK);
    colsum_kernel<<<cg, 256>>>(X, N, K);
    base_kernel<<<1, 256>>>(N, K);
    int G = N / 128;
    int tri = G * (G + 1) / 2;
    gemm_nt_kernel<<<tri, 256>>>(X, X, Gptr, N, N, K, nullptr, 2);
    prefixmin_kernel<<<N, 256>>>(N);
    scan_kernel<<<1, 32>>>(N);
    lamb_kernel<<<N, 256>>>(N, lamb_out);
}

extern "C" void kernel_launch(void* const* d_in, const int* in_sizes, int n_in,
                              void* d_out, int out_size) {
    const float* x  = (const float*)d_in[0];
    const float* W0 = (const float*)d_in[1];
    const float* b0 = (const float*)d_in[2];
    const float* W1 = (const float*)d_in[3];
    const float* b1 = (const float*)d_in[4];

    int DH   = in_sizes[2];            // 2048
    int DOUT = in_sizes[4];            // 1024
    int DIN  = in_sizes[1] / DH;       // 2048
    int N    = in_sizes[0] / DIN;      // 2048

    float* out   = (float*)d_out;
    float* outH  = out;                          // h: [N, DOUT]
    float* lamb0 = out + (size_t)N * DOUT;       // lambs[0]
    float* lamb1 = lamb0 + N;                    // lambs[1]

    float* Gptr = nullptr;
    float* Hptr = nullptr;
    cudaGetSymbolAddress((void**)&Gptr, g_G);
    cudaGetSymbolAddress((void**)&Hptr, g_H);

    // ---- layer 0 ----
    run_codebook(x, N, DIN, lamb0, Gptr);
    {
        dim3 g0(DH / 128, N / 128);
        gemm_nt_kernel<<<g0, 256>>>(x, W0, Hptr, N, DH, DIN, b0, 1);
    }

    // ---- layer 1 ----
    run_codebook(Hptr, N, DH, lamb1, Gptr);
    {
        dim3 g1(DOUT / 128, N / 128);
        gemm_nt_kernel<<<g1, 256>>>(Hptr, W1, outH, N, DOUT, DH, b1, 1);
    }
}

// round 3
// speedup vs baseline: 5.0330x; 2.4588x over previous
#include <cuda_runtime.h>
#include <math.h>
#include <stdint.h>

// SOMFNN: two layers of (ALMMo codebook lamb) + sigmoid(Linear)
// stau = base/2 (scalar); prototypes are input samples -> all distances from
// Gram = X X^T; min-distance-over-all-predecessors shortcut for new rules.
// GEMMs on tensor cores (tf32 mma.sync, RNA-rounded inputs).

#define MAXN 2048
#define MAXD 2048
#define NCHUNK 16
#define LDSW 20   // padded floats per smem row (16 data + 4 pad)

__device__ float g_G[(size_t)MAXN * MAXN];
__device__ float g_H[(size_t)MAXN * MAXD];
__device__ float g_SEN[MAXN];
__device__ float g_colpart[NCHUNK][MAXD];
__device__ float g_base[2];
__device__ float g_mind[MAXN];
__device__ int   g_rules[MAXN];
__device__ int   g_protos[MAXN];
__device__ int   g_count[1];

// ---------------- block reductions ----------------
__device__ __forceinline__ float blockReduceSum(float v) {
    __shared__ float sh[32];
    int lane = threadIdx.x & 31, wid = threadIdx.x >> 5;
#pragma unroll
    for (int o = 16; o; o >>= 1) v += __shfl_down_sync(0xffffffffu, v, o);
    __syncthreads();
    if (lane == 0) sh[wid] = v;
    __syncthreads();
    if (wid == 0) {
        int nw = (blockDim.x + 31) >> 5;
        v = (lane < nw) ? sh[lane] : 0.0f;
#pragma unroll
        for (int o = 16; o; o >>= 1) v += __shfl_down_sync(0xffffffffu, v, o);
    }
    return v;
}

__device__ __forceinline__ float blockReduceMin(float v) {
    __shared__ float sh[32];
    int lane = threadIdx.x & 31, wid = threadIdx.x >> 5;
#pragma unroll
    for (int o = 16; o; o >>= 1) v = fminf(v, __shfl_down_sync(0xffffffffu, v, o));
    __syncthreads();
    if (lane == 0) sh[wid] = v;
    __syncthreads();
    if (wid == 0) {
        int nw = (blockDim.x + 31) >> 5;
        v = (lane < nw) ? sh[lane] : INFINITY;
#pragma unroll
        for (int o = 16; o; o >>= 1) v = fminf(v, __shfl_down_sync(0xffffffffu, v, o));
    }
    return v;
}

// ---------------- small prep kernels ----------------
__global__ void rowsumsq_kernel(const float* __restrict__ X, int K) {
    int i = blockIdx.x;
    const float4* row = (const float4*)(X + (size_t)i * K);
    float s = 0.0f;
    for (int k = threadIdx.x; k < (K >> 2); k += blockDim.x) {
        float4 v = row[k];
        s += v.x * v.x + v.y * v.y + v.z * v.z + v.w * v.w;
    }
    s = blockReduceSum(s);
    if (threadIdx.x == 0) g_SEN[i] = s;
}

__global__ void colsum_kernel(const float* __restrict__ X, int N, int K) {
    int c = blockIdx.x * blockDim.x + threadIdx.x;
    int chunk = blockIdx.y;
    if (c >= K) return;
    int r0 = chunk * (N / NCHUNK), r1 = r0 + N / NCHUNK;
    float s = 0.0f;
    for (int i = r0; i < r1; i++) s += X[(size_t)i * K + c];
    g_colpart[chunk][c] = s;
}

__global__ void base_kernel(int N, int K) {
    float invN = 1.0f / (float)N;
    float s1 = 0.0f, s2 = 0.0f;
    for (int i = threadIdx.x; i < N; i += blockDim.x) s1 += g_SEN[i];
    for (int c = threadIdx.x; c < K; c += blockDim.x) {
        float cs = 0.0f;
#pragma unroll
        for (int h = 0; h < NCHUNK; h++) cs += g_colpart[h][c];
        float m = cs * invN;
        s2 += m * m;
    }
    s1 = blockReduceSum(s1);
    __syncthreads();
    s2 = blockReduceSum(s2);
    if (threadIdx.x == 0) {
        float base = s1 * invN - s2;
        g_base[0] = base;
        g_base[1] = 0.5f * base;
    }
}

// ---------------- tensor-core helpers ----------------
__device__ __forceinline__ unsigned f2tf(float f) {
    unsigned u;
    asm("cvt.rna.tf32.f32 %0, %1;" : "=r"(u) : "f"(f));
    return u;
}

__device__ __forceinline__ unsigned smaddr(const void* p) {
    unsigned r;
    asm("{.reg .u64 t; cvta.to.shared.u64 t, %1; cvt.u32.u64 %0, t;}"
        : "=r"(r) : "l"(p));
    return r;
}

__device__ __forceinline__ void ldsm4(unsigned& r0, unsigned& r1, unsigned& r2,
                                      unsigned& r3, unsigned a) {
    asm volatile("ldmatrix.sync.aligned.m8n8.x4.shared.b16 {%0,%1,%2,%3},[%4];"
                 : "=r"(r0), "=r"(r1), "=r"(r2), "=r"(r3) : "r"(a));
}

__device__ __forceinline__ void mma_tf32(float* c, const unsigned* a, const unsigned* b) {
    asm volatile(
        "mma.sync.aligned.m16n8k8.row.col.f32.tf32.tf32.f32 "
        "{%0,%1,%2,%3},{%4,%5,%6,%7},{%8,%9},{%0,%1,%2,%3};"
        : "+f"(c[0]), "+f"(c[1]), "+f"(c[2]), "+f"(c[3])
        : "r"(a[0]), "r"(a[1]), "r"(a[2]), "r"(a[3]), "r"(b[0]), "r"(b[1]));
}

// ---------------- tf32 tensor-core GEMM (NT) --------------------------------
// C[i,j] = sum_k A[i,k]*B[j,k]. mode 0: plain, 1: bias+sigmoid, 2: symmetric
// Gram (A==B, triangular 1D grid, mirrored store). M,N mult 128, K mult 16.
__global__ void __launch_bounds__(256, 2)
gemm_tc_kernel(const float* __restrict__ A, const float* __restrict__ B,
               float* __restrict__ C, int M, int N, int K,
               const float* __restrict__ bias, int mode) {
    __shared__ unsigned As[2][128 * LDSW];
    __shared__ unsigned Bs[2][128 * LDSW];
    const int tid = threadIdx.x;
    const int wid = tid >> 5, lane = tid & 31;

    int bi, bj;
    if (mode == 2) {
        int id = blockIdx.x;
        bi = (int)((sqrtf(8.0f * (float)id + 1.0f) - 1.0f) * 0.5f);
        while ((bi + 1) * (bi + 2) / 2 <= id) bi++;
        while (bi * (bi + 1) / 2 > id) bi--;
        bj = id - bi * (bi + 1) / 2;
    } else {
        bi = blockIdx.y; bj = blockIdx.x;
    }
    const int rowBase = bi << 7, colBase = bj << 7;

    // global loads: each thread 2 float4 from A, 2 from B per K-tile
    const int lrow = tid >> 2;        // 0..63
    const int lc4  = tid & 3;         // float4 slot within 16-float row chunk
    const float* Ap0 = A + (size_t)(rowBase + lrow) * K + lc4 * 4;
    const float* Ap1 = A + (size_t)(rowBase + lrow + 64) * K + lc4 * 4;
    const float* Bp0 = B + (size_t)(colBase + lrow) * K + lc4 * 4;
    const float* Bp1 = B + (size_t)(colBase + lrow + 64) * K + lc4 * 4;
    const int sA0 = lrow * LDSW + lc4 * 4;
    const int sA1 = (lrow + 64) * LDSW + lc4 * 4;

    // warp tiling: 4(m) x 2(n), warp tile 32x64
    const int wm = (wid & 3) * 32, wn = (wid >> 2) * 64;
    const int aRow = wm + (lane & 15);
    const int aKof = (lane >> 4) * 4;
    const int bRow = wn + ((lane >> 4) & 1) * 8 + (lane & 7);
    const int bKof = ((lane >> 3) & 1) * 4;

    const unsigned aBase = smaddr(&As[0][0]);
    const unsigned bBase = smaddr(&Bs[0][0]);
    const unsigned bufStride = 128 * LDSW * 4;

    float acc[2][8][4];
#pragma unroll
    for (int fm = 0; fm < 2; fm++)
#pragma unroll
        for (int fn = 0; fn < 8; fn++)
#pragma unroll
            for (int q = 0; q < 4; q++) acc[fm][fn][q] = 0.0f;

    // preload tile 0
    float4 fa0 = *(const float4*)Ap0;
    float4 fa1 = *(const float4*)Ap1;
    float4 fb0 = *(const float4*)Bp0;
    float4 fb1 = *(const float4*)Bp1;
    {
        unsigned* da = &As[0][0]; unsigned* db = &Bs[0][0];
        da[sA0] = f2tf(fa0.x); da[sA0+1] = f2tf(fa0.y); da[sA0+2] = f2tf(fa0.z); da[sA0+3] = f2tf(fa0.w);
        da[sA1] = f2tf(fa1.x); da[sA1+1] = f2tf(fa1.y); da[sA1+2] = f2tf(fa1.z); da[sA1+3] = f2tf(fa1.w);
        db[sA0] = f2tf(fb0.x); db[sA0+1] = f2tf(fb0.y); db[sA0+2] = f2tf(fb0.z); db[sA0+3] = f2tf(fb0.w);
        db[sA1] = f2tf(fb1.x); db[sA1+1] = f2tf(fb1.y); db[sA1+2] = f2tf(fb1.z); db[sA1+3] = f2tf(fb1.w);
    }
    __syncthreads();

    const int nt = K >> 4;
    int buf = 0;
    for (int t = 0; t < nt; t++) {
        if (t + 1 < nt) {
            fa0 = *(const float4*)(Ap0 + (size_t)(t + 1) * 16);
            fa1 = *(const float4*)(Ap1 + (size_t)(t + 1) * 16);
            fb0 = *(const float4*)(Bp0 + (size_t)(t + 1) * 16);
            fb1 = *(const float4*)(Bp1 + (size_t)(t + 1) * 16);
        }
        const unsigned aB = aBase + buf * bufStride;
        const unsigned bB = bBase + buf * bufStride;
#pragma unroll
        for (int kg = 0; kg < 2; kg++) {
            unsigned afr[2][4];
#pragma unroll
            for (int fm = 0; fm < 2; fm++) {
                unsigned ad = aB + (unsigned)(((aRow + fm * 16) * LDSW + kg * 8 + aKof) * 4);
                ldsm4(afr[fm][0], afr[fm][1], afr[fm][2], afr[fm][3], ad);
            }
            unsigned bfr[8][2];
#pragma unroll
            for (int fp = 0; fp < 4; fp++) {
                unsigned bd = bB + (unsigned)(((bRow + fp * 16) * LDSW + kg * 8 + bKof) * 4);
                ldsm4(bfr[2*fp][0], bfr[2*fp][1], bfr[2*fp+1][0], bfr[2*fp+1][1], bd);
            }
#pragma unroll
            for (int fm = 0; fm < 2; fm++)
#pragma unroll
                for (int fn = 0; fn < 8; fn++)
                    mma_tf32(acc[fm][fn], afr[fm], bfr[fn]);
        }
        if (t + 1 < nt) {
            int nb = buf ^ 1;
            unsigned* da = &As[nb][0]; unsigned* db = &Bs[nb][0];
            da[sA0] = f2tf(fa0.x); da[sA0+1] = f2tf(fa0.y); da[sA0+2] = f2tf(fa0.z); da[sA0+3] = f2tf(fa0.w);
            da[sA1] = f2tf(fa1.x); da[sA1+1] = f2tf(fa1.y); da[sA1+2] = f2tf(fa1.z); da[sA1+3] = f2tf(fa1.w);
            db[sA0] = f2tf(fb0.x); db[sA0+1] = f2tf(fb0.y); db[sA0+2] = f2tf(fb0.z); db[sA0+3] = f2tf(fb0.w);
            db[sA1] = f2tf(fb1.x); db[sA1+1] = f2tf(fb1.y); db[sA1+2] = f2tf(fb1.z); db[sA1+3] = f2tf(fb1.w);
            __syncthreads();
            buf = nb;
        }
    }

    // epilogue: c0,c1 at (row, 2c..2c+1), c2,c3 at (row+8, same cols)
    const int crow = lane >> 2;
    const int ccol = (lane & 3) * 2;
    if (mode == 1) {
#pragma unroll
        for (int fm = 0; fm < 2; fm++) {
            int rr = rowBase + wm + fm * 16 + crow;
#pragma unroll
            for (int fn = 0; fn < 8; fn++) {
                int cc = colBase + wn + fn * 8 + ccol;
                float b0v = bias[cc], b1v = bias[cc + 1];
                float2 v;
                v.x = 1.0f / (1.0f + expf(-(acc[fm][fn][0] + b0v)));
                v.y = 1.0f / (1.0f + expf(-(acc[fm][fn][1] + b1v)));
                *(float2*)&C[(size_t)rr * N + cc] = v;
                v.x = 1.0f / (1.0f + expf(-(acc[fm][fn][2] + b0v)));
                v.y = 1.0f / (1.0f + expf(-(acc[fm][fn][3] + b1v)));
                *(float2*)&C[(size_t)(rr + 8) * N + cc] = v;
            }
        }
    } else {
#pragma unroll
        for (int fm = 0; fm < 2; fm++) {
            int rr = rowBase + wm + fm * 16 + crow;
#pragma unroll
            for (int fn = 0; fn < 8; fn++) {
                int cc = colBase + wn + fn * 8 + ccol;
                float2 v0 = make_float2(acc[fm][fn][0], acc[fm][fn][1]);
                float2 v1 = make_float2(acc[fm][fn][2], acc[fm][fn][3]);
                *(float2*)&C[(size_t)rr * N + cc] = v0;
                *(float2*)&C[(size_t)(rr + 8) * N + cc] = v1;
            }
        }
        if (mode == 2 && bi != bj) {
#pragma unroll
            for (int fm = 0; fm < 2; fm++) {
                int rr = rowBase + wm + fm * 16 + crow;
#pragma unroll
                for (int fn = 0; fn < 8; fn++) {
                    int cc = colBase + wn + fn * 8 + ccol;
                    C[(size_t)cc * N + rr]           = acc[fm][fn][0];
                    C[(size_t)(cc + 1) * N + rr]     = acc[fm][fn][1];
                    C[(size_t)cc * N + rr + 8]       = acc[fm][fn][2];
                    C[(size_t)(cc + 1) * N + rr + 8] = acc[fm][fn][3];
                }
            }
        }
    }
}

// ---------------- prefix row-min: min_{j<i} D[i,j] ----------------
__global__ void prefixmin_kernel(int N) {
    int i = blockIdx.x;
    float si = g_SEN[i];
    const float* Gi = g_G + (size_t)i * N;
    float m = INFINITY;
    for (int j = threadIdx.x; j < i; j += blockDim.x) {
        float d = si + g_SEN[j] - 2.0f * Gi[j];
        m = fminf(m, d);
    }
    m = blockReduceMin(m);
    if (threadIdx.x == 0) g_mind[i] = m;
}

// ---------------- sequential rule-creation scan (1 warp, ballot fast path) --
__global__ void scan_kernel(int N) {
    const int lane = threadIdx.x;
    const float DELTA = 0.13533528323661270f;  // exp(-2)
    float stau = g_base[1];
    bool st_ok = (stau > 0.0f) && (stau < 3.0e38f);
    int count = 0;

    for (int i0 = 0; i0 < N; i0 += 32) {
        int lim = (N - i0 < 32) ? (N - i0) : 32;
        int myi = i0 + lane;
        bool cert = false;
        if (myi < N && st_ok) cert = (expf(-g_mind[myi] / stau) < DELTA);
        unsigned mask = __ballot_sync(0xffffffffu, cert);
        unsigned need = (lim == 32) ? 0xffffffffu : ((1u << lim) - 1u);
        if ((mask & need) == need) {
            if (lane < lim) {
                g_rules[myi] = count + lane;
                g_protos[count + lane] = myi;
            }
            count += lim;
            continue;
        }
        for (int t = 0; t < lim; t++) {
            int i = i0 + t;
            bool newr;
            int slot = 0;
            if (count == 0 || ((mask >> t) & 1u)) {
                newr = true;
            } else {
                float si = g_SEN[i];
                const float* Gi = g_G + (size_t)i * N;
                float best = -INFINITY;
                int bestr = 0x7fffffff;
                for (int r = lane; r < count; r += 32) {
                    int pr = g_protos[r];
                    float d = si + g_SEN[pr] - 2.0f * Gi[pr];
                    float dens = expf(-d / stau);
                    if (dens > best) { best = dens; bestr = r; }
                }
#pragma unroll
                for (int off = 16; off; off >>= 1) {
                    float ob = __shfl_down_sync(0xffffffffu, best, off);
                    int obr = __shfl_down_sync(0xffffffffu, bestr, off);
                    if (ob > best || (ob == best && obr < bestr)) { best = ob; bestr = obr; }
                }
                best  = __shfl_sync(0xffffffffu, best, 0);
                bestr = __shfl_sync(0xffffffffu, bestr, 0);
                newr = (best < DELTA);
                slot = bestr;
            }
            if (newr) slot = count;
            if (lane == 0) g_rules[i] = slot;
            if (newr) {
                if (lane == 0) g_protos[count] = i;
                count++;
            }
        }
    }
    if (lane == 0) g_count[0] = count;
}

// ---------------- final normalized densities ----------------
__global__ void lamb_kernel(int N, float* __restrict__ out) {
    int n = blockIdx.x;
    int count = g_count[0];
    float stau = g_base[1];
    float sn = g_SEN[n];
    const float* Gn = g_G + (size_t)n * N;
    float s = 0.0f;
    for (int r = threadIdx.x; r < count; r += blockDim.x) {
        int pr = g_protos[r];
        float d = sn + g_SEN[pr] - 2.0f * Gn[pr];
        s += expf(-d / stau);
    }
    s = blockReduceSum(s);
    if (threadIdx.x == 0) {
        int pr = g_protos[g_rules[n]];
        float d = sn + g_SEN[pr] - 2.0f * Gn[pr];
        out[n] = expf(-d / stau) / s;
    }
}

// ---------------- host-side orchestration ----------------
static void run_codebook(const float* X, int N, int K, float* lamb_out, float* Gptr) {
    rowsumsq_kernel<<<N, 256>>>(X, K);
    dim3 cg((K + 255) / 256, NCHUNK);
    colsum_kernel<<<cg, 256>>>(X, N, K);
    base_kernel<<<1, 256>>>(N, K);
    int G = N / 128;
    int tri = G * (G + 1) / 2;
    gemm_tc_kernel<<<tri, 256>>>(X, X, Gptr, N, N, K, nullptr, 2);
    prefixmin_kernel<<<N, 256>>>(N);
    scan_kernel<<<1, 32>>>(N);
    lamb_kernel<<<N, 256>>>(N, lamb_out);
}

extern "C" void kernel_launch(void* const* d_in, const int* in_sizes, int n_in,
                              void* d_out, int out_size) {
    const float* x  = (const float*)d_in[0];
    const float* W0 = (const float*)d_in[1];
    const float* b0 = (const float*)d_in[2];
    const float* W1 = (const float*)d_in[3];
    const float* b1 = (const float*)d_in[4];

    int DH   = in_sizes[2];            // 2048
    int DOUT = in_sizes[4];            // 1024
    int DIN  = in_sizes[1] / DH;       // 2048
    int N    = in_sizes[0] / DIN;      // 2048

    float* out   = (float*)d_out;
    float* outH  = out;                          // h: [N, DOUT]
    float* lamb0 = out + (size_t)N * DOUT;       // lambs[0]
    float* lamb1 = lamb0 + N;                    // lambs[1]

    float* Gptr = nullptr;
    float* Hptr = nullptr;
    cudaGetSymbolAddress((void**)&Gptr, g_G);
    cudaGetSymbolAddress((void**)&Hptr, g_H);

    // ---- layer 0 ----
    run_codebook(x, N, DIN, lamb0, Gptr);
    {
        dim3 g0(DH / 128, N / 128);
        gemm_tc_kernel<<<g0, 256>>>(x, W0, Hptr, N, DH, DIN, b0, 1);
    }

    // ---- layer 1 ----
    run_codebook(Hptr, N, DH, lamb1, Gptr);
    {
        dim3 g1(DOUT / 128, N / 128);
        gemm_tc_kernel<<<g1, 256>>>(Hptr, W1, outH, N, DOUT, DH, b1, 1);
    }
}